// round 1
// baseline (speedup 1.0000x reference)
#include <cuda_runtime.h>
#include <cuda_bf16.h>

// S4D kernel: K[h, l] = 2 * Re( sum_n Ck[h,n] * exp(dtA[h,n] * l) )
//   dt  = exp(log_dt[h])
//   A   = -exp(log_A_real) + i*A_imag
//   Ck  = C * (exp(dt*A) - 1) / A
//
// Factorization: l = a + 64*b  (a in [0,64), b in [0,64), L = 4096)
//   w    = exp(dt*A)
//   wJ   = w^64
//   P[n][a] = 2 * Ck_n * w^a        (sign/scale folded in)
//   Q[n][b] = wJ^b
//   K[h, a + 64*b] = sum_n ( Qr*Pr - Qi*Pi )
//
// One block per h. Phase 1: 64 threads build the P/Q tables by complex
// recurrence (only ~2 transcendental evals per mode). Phase 2: 256 threads
// do the 64x64x(32 complex) contraction with 4x4 register tiles.

#define N2C 32
#define LA  64   // inner stride (a)
#define LB  64   // outer count (b); L = LA*LB = 4096

__global__ __launch_bounds__(256, 6)
void s4d_kernel(const float* __restrict__ log_dt,
                const float* __restrict__ C,
                const float* __restrict__ log_A_real,
                const float* __restrict__ A_imag,
                float* __restrict__ out)
{
    __shared__ float2 Psh[N2C][LA];   // 16 KB
    __shared__ float2 Qsh[N2C][LB];   // 16 KB

    const int h   = blockIdx.x;
    const int tid = threadIdx.x;

    // ---------------- Phase 1: build tables ----------------
    if (tid < 2 * N2C) {
        const int  n   = tid & (N2C - 1);
        const bool doQ = tid >= N2C;

        const float dt = expf(log_dt[h]);
        const float Ar = -expf(log_A_real[h * N2C + n]);
        const float Ai = A_imag[h * N2C + n];
        const float dr = dt * Ar;     // Re(dt*A)  (negative)
        const float di = dt * Ai;     // Im(dt*A)

        if (!doQ) {
            // w = exp(dt*A)
            float er = expf(dr), s, c;
            sincosf(di, &s, &c);
            const float wr = er * c, wi = er * s;

            // g = (w - 1) / A   (complex divide)
            const float inv = 1.0f / (Ar * Ar + Ai * Ai);
            const float nr = wr - 1.0f, ni = wi;
            const float gr = (nr * Ar + ni * Ai) * inv;
            const float gi = (ni * Ar - nr * Ai) * inv;

            // P0 = 2 * C * g
            const float Cr = C[(h * N2C + n) * 2 + 0];
            const float Ci = C[(h * N2C + n) * 2 + 1];
            float pr = 2.0f * (Cr * gr - Ci * gi);
            float pi = 2.0f * (Cr * gi + Ci * gr);

            #pragma unroll 4
            for (int a = 0; a < LA; a++) {
                Psh[n][a] = make_float2(pr, pi);
                const float t = pr * wr - pi * wi;
                pi = pr * wi + pi * wr;
                pr = t;
            }
        } else {
            // wJ = w^64 = exp(64 * dt * A), computed directly for accuracy
            float er = expf(64.0f * dr), s, c;
            sincosf(64.0f * di, &s, &c);
            const float wJr = er * c, wJi = er * s;

            float qr = 1.0f, qi = 0.0f;
            #pragma unroll 4
            for (int b = 0; b < LB; b++) {
                Qsh[n][b] = make_float2(qr, qi);
                const float t = qr * wJr - qi * wJi;
                qi = qr * wJi + qi * wJr;
                qr = t;
            }
        }
    }
    __syncthreads();

    // ---------------- Phase 2: 64x64 contraction ----------------
    // Thread grid 16x16; each thread owns a 4(b) x 4(a) output tile.
    const int tx = tid & 15;
    const int ty = tid >> 4;
    const int a0 = tx * 4;
    const int b0 = ty * 4;

    float acc[4][4];
    #pragma unroll
    for (int i = 0; i < 4; i++)
        #pragma unroll
        for (int j = 0; j < 4; j++)
            acc[i][j] = 0.0f;

    #pragma unroll
    for (int n = 0; n < N2C; n++) {
        float2 p[4], q[4];
        #pragma unroll
        for (int j = 0; j < 4; j++) p[j] = Psh[n][a0 + j];
        #pragma unroll
        for (int i = 0; i < 4; i++) q[i] = Qsh[n][b0 + i];

        #pragma unroll
        for (int i = 0; i < 4; i++)
            #pragma unroll
            for (int j = 0; j < 4; j++)
                acc[i][j] = fmaf(q[i].x, p[j].x,
                            fmaf(-q[i].y, p[j].y, acc[i][j]));
    }

    // ---------------- Store: STG.128, coalesced ----------------
    float* o = out + (size_t)h * (LA * LB);
    #pragma unroll
    for (int i = 0; i < 4; i++) {
        float4 v = make_float4(acc[i][0], acc[i][1], acc[i][2], acc[i][3]);
        *reinterpret_cast<float4*>(o + (b0 + i) * LA + a0) = v;
    }
}

extern "C" void kernel_launch(void* const* d_in, const int* in_sizes, int n_in,
                              void* d_out, int out_size)
{
    const float* log_dt     = (const float*)d_in[0];
    const float* C          = (const float*)d_in[1];
    const float* log_A_real = (const float*)d_in[2];
    const float* A_imag     = (const float*)d_in[3];
    float*       out        = (float*)d_out;

    const int H = in_sizes[0];   // 1024
    s4d_kernel<<<H, 256>>>(log_dt, C, log_A_real, A_imag, out);
}